// round 8
// baseline (speedup 1.0000x reference)
#include <cuda_runtime.h>

#define NQ_MAX 131072
#define E_MAX  2097152
#define FULL 0xffffffffu

// ---------- device scratch (no allocations allowed) ----------
__device__ __align__(16) float g_u[64];        // W^T wq
__device__ __align__(16) float g_v[64];        // W^T wk
__device__ float g_C;                          // proj_b.(wq+wk) + attend_b
__device__ __align__(16) float g_sq[NQ_MAX];   // per-query scalar
__device__ __align__(16) float g_sk[NQ_MAX];   // per-key scalar
__device__ int   g_count[NQ_MAX];
__device__ int   g_off[NQ_MAX + 1];
__device__ int   g_cursor[NQ_MAX];
__device__ int   g_bsum[1024];
__device__ __align__(16) int2  g_pair[E_MAX];  // sorted (ki, exp(leaky(logit)) bits)
__device__ __align__(16) float g_kp[(size_t)NQ_MAX * 64];  // kv_proj

// ---------- kernels ----------
// zero histogram (whole grid) + compute u, v, C (block 0)
__global__ void k_prep(const float* __restrict__ W, const float* __restrict__ pb,
                       const float* __restrict__ aw, const float* __restrict__ ab,
                       int Nq) {
    int i = blockIdx.x * blockDim.x + threadIdx.x;
    if (i < Nq) g_count[i] = 0;
    if (blockIdx.x == 0) {
        int j = threadIdx.x;
        if (j < 64) {
            float uj = 0.f, vj = 0.f;
            #pragma unroll
            for (int r = 0; r < 64; r++) {
                float w = W[r * 64 + j];
                uj += w * aw[r];
                vj += w * aw[64 + r];
            }
            g_u[j] = uj;
            g_v[j] = vj;
        }
        if (j == 0) {
            float c = ab[0];
            for (int r = 0; r < 64; r++) c += pb[r] * (aw[r] + aw[64 + r]);
            g_C = c;
        }
    }
}

// warp per query row: sq = q . u
__global__ void k_node_scalars(const float* __restrict__ q, int Nq) {
    int w = (blockIdx.x * blockDim.x + threadIdx.x) >> 5;
    int lane = threadIdx.x & 31;
    if (w >= Nq) return;
    float2 a = *(const float2*)(q + (size_t)w * 64 + lane * 2);
    float2 b = *(const float2*)(g_u + lane * 2);
    float acc = a.x * b.x + a.y * b.y;
    #pragma unroll
    for (int o = 16; o; o >>= 1) acc += __shfl_xor_sync(FULL, acc, o);
    if (lane == 0) g_sq[w] = acc;
}

// degree histogram over qi, 4 edges per thread
__global__ void k_edge1(const int* __restrict__ eidx, int E) {
    int j4 = (blockIdx.x * blockDim.x + threadIdx.x) * 4;
    if (j4 + 3 < E) {
        int4 v = *(const int4*)(eidx + j4);
        atomicAdd(&g_count[v.x], 1);
        atomicAdd(&g_count[v.y], 1);
        atomicAdd(&g_count[v.z], 1);
        atomicAdd(&g_count[v.w], 1);
    } else {
        for (int j = j4; j < E; j++) atomicAdd(&g_count[eidx[j]], 1);
    }
}

// block-level exclusive scan (1024 threads, shuffle-based) -> g_off (local), g_bsum
__global__ void k_scan_a(int Nq) {
    __shared__ int wsum[32];
    int tid  = threadIdx.x;
    int lane = tid & 31;
    int wid  = tid >> 5;
    int i = blockIdx.x * 1024 + tid;
    int x = (i < Nq) ? g_count[i] : 0;
    int v = x;
    #pragma unroll
    for (int o = 1; o < 32; o <<= 1) {
        int t = __shfl_up_sync(FULL, v, o);
        if (lane >= o) v += t;
    }
    if (lane == 31) wsum[wid] = v;
    __syncthreads();
    if (wid == 0) {
        int w = wsum[lane];
        #pragma unroll
        for (int o = 1; o < 32; o <<= 1) {
            int t = __shfl_up_sync(FULL, w, o);
            if (lane >= o) w += t;
        }
        wsum[lane] = w;
    }
    __syncthreads();
    int incl = v + (wid ? wsum[wid - 1] : 0);
    if (i < Nq) g_off[i] = incl - x;
    if (tid == 1023) g_bsum[blockIdx.x] = incl;
}

// fused: scan g_bsum (per-block recompute, nb <= 1024) + add to offsets + init cursor
__global__ void k_scan_c(int Nq, int E, int nb) {
    __shared__ int spref[1024];
    int tid = threadIdx.x;       // 256 threads
    for (int t = tid; t < nb; t += 256) spref[t] = g_bsum[t];
    __syncthreads();
    for (int off = 1; off < nb; off <<= 1) {
        int t0 = (tid < nb && tid >= off) ? spref[tid - off] : 0;
        int t1 = (256 + tid < nb && 256 + tid >= off) ? spref[256 + tid - off] : 0;
        int t2 = (512 + tid < nb && 512 + tid >= off) ? spref[512 + tid - off] : 0;
        int t3 = (768 + tid < nb && 768 + tid >= off) ? spref[768 + tid - off] : 0;
        __syncthreads();
        if (tid < nb) spref[tid] += t0;
        if (256 + tid < nb) spref[256 + tid] += t1;
        if (512 + tid < nb) spref[512 + tid] += t2;
        if (768 + tid < nb) spref[768 + tid] += t3;
        __syncthreads();
    }
    int i = blockIdx.x * blockDim.x + tid;
    if (i < Nq) {
        int b = i >> 10;
        int off = g_off[i] + (b ? spref[b - 1] : 0);
        g_off[i] = off;
        g_cursor[i] = off;
    }
    if (i == 0) g_off[Nq] = E;
}

// counting-sort scatter: compute exp(leaky(logit)), place (ki, exp) pair into
// qi-contiguous segment. 4 edges per thread for MLP on the atomic->store chains.
__global__ void k_scatter(const int* __restrict__ eidx, int E) {
    int j4 = (blockIdx.x * blockDim.x + threadIdx.x) * 4;
    if (((E & 3) == 0) && (j4 + 3 < E)) {
        int4 qq = *(const int4*)(eidx + j4);
        int4 kk = *(const int4*)(eidx + E + j4);
        float e0 = g_sq[qq.x] + g_sk[kk.x] + g_C;
        float e1 = g_sq[qq.y] + g_sk[kk.y] + g_C;
        float e2 = g_sq[qq.z] + g_sk[kk.z] + g_C;
        float e3 = g_sq[qq.w] + g_sk[kk.w] + g_C;
        e0 = __expf(e0 > 0.f ? e0 : 0.2f * e0);
        e1 = __expf(e1 > 0.f ? e1 : 0.2f * e1);
        e2 = __expf(e2 > 0.f ? e2 : 0.2f * e2);
        e3 = __expf(e3 > 0.f ? e3 : 0.2f * e3);
        int p0 = atomicAdd(&g_cursor[qq.x], 1);
        int p1 = atomicAdd(&g_cursor[qq.y], 1);
        int p2 = atomicAdd(&g_cursor[qq.z], 1);
        int p3 = atomicAdd(&g_cursor[qq.w], 1);
        g_pair[p0] = make_int2(kk.x, __float_as_int(e0));
        g_pair[p1] = make_int2(kk.y, __float_as_int(e1));
        g_pair[p2] = make_int2(kk.z, __float_as_int(e2));
        g_pair[p3] = make_int2(kk.w, __float_as_int(e3));
    } else {
        for (int j = j4; j < E && j < j4 + 4; j++) {
            int qi = eidx[j];
            int ki = eidx[E + j];
            float ev = g_sq[qi] + g_sk[ki] + g_C;
            ev = __expf(ev > 0.f ? ev : 0.2f * ev);
            int pos = atomicAdd(&g_cursor[qi], 1);
            g_pair[pos] = make_int2(ki, __float_as_int(ev));
        }
    }
}

// kv_proj = kv @ W^T + b (Nk x 64), 128 rows per block. Also fused: sk = kv . v
__global__ void k_gemm(const float* __restrict__ x, const float* __restrict__ W,
                       const float* __restrict__ b, int Nk) {
    __shared__ __align__(16) float Wts[64 * 64];  // Wts[j*64+i] = W[i*64+j]
    __shared__ __align__(16) float xs[16 * 64];
    __shared__ __align__(16) float vs[64];
    int tid = threadIdx.x;
    if (tid < 64) vs[tid] = g_v[tid];
    for (int t = tid * 4; t < 4096; t += 1024) {
        float4 w = *(const float4*)(W + t);
        int i = t >> 6, j = t & 63;
        Wts[(j + 0) * 64 + i] = w.x;
        Wts[(j + 1) * 64 + i] = w.y;
        Wts[(j + 2) * 64 + i] = w.z;
        Wts[(j + 3) * 64 + i] = w.w;
    }
    int r  = tid >> 4;   // 0..15 row within tile
    int cg = tid & 15;   // 0..15 column group (4 cols)
    float4 bias = *(const float4*)(b + cg * 4);
    int base = blockIdx.x * 128;
    for (int it = 0; it < 8; it++) {
        __syncthreads();   // covers Wts/vs on it=0, xs reuse otherwise
        int row = base + it * 16 + r;
        float4 xv4 = (row < Nk) ? *(const float4*)(x + (size_t)row * 64 + cg * 4)
                                : make_float4(0.f, 0.f, 0.f, 0.f);
        *(float4*)(xs + r * 64 + cg * 4) = xv4;
        // fused sk: dot of this row with v, reduced over the 16-lane group
        float4 vv = *(const float4*)(vs + cg * 4);
        float part = xv4.x * vv.x + xv4.y * vv.y + xv4.z * vv.z + xv4.w * vv.w;
        #pragma unroll
        for (int o = 8; o; o >>= 1) part += __shfl_xor_sync(FULL, part, o);
        if (cg == 0 && row < Nk) g_sk[row] = part;
        __syncthreads();
        float4 acc = bias;
        #pragma unroll
        for (int j = 0; j < 64; j++) {
            float  xv = xs[r * 64 + j];
            float4 wv = *(const float4*)(Wts + j * 64 + cg * 4);
            acc.x += xv * wv.x; acc.y += xv * wv.y;
            acc.z += xv * wv.z; acc.w += xv * wv.w;
        }
        if (row < Nk) *(float4*)(g_kp + (size_t)row * 64 + cg * 4) = acc;
    }
}

// warp per query node. Half-warp float4 gathers: lanes 0-15 handle even edge,
// lanes 16-31 the odd edge (variable-src shfl broadcast). 2 edges per step,
// unrolled x4 -> 4 independent LDG.128 in flight. Out-of-range lanes carry
// ex=0, kn=0 (row 0 = harmless dummy read), so no remainder special-casing.
__global__ void k_agg(float* __restrict__ out, int Nq) {
    int w = (blockIdx.x * blockDim.x + threadIdx.x) >> 5;
    int lane = threadIdx.x & 31;
    if (w >= Nq) return;
    int half = lane >> 4;          // 0 or 1
    int hl   = lane & 15;          // lane within half
    int s = g_off[w], e = g_off[w + 1];
    const float4* kp4 = (const float4*)g_kp;   // row k spans kp4[k*16 .. k*16+15]
    float sum = 0.f;
    float4 acc = make_float4(0.f, 0.f, 0.f, 0.f);
    for (int base = s; base < e; base += 32) {
        int i = base + lane;
        float ex = 0.f; int kn = 0;
        if (i < e) {
            int2 p = g_pair[i];
            kn = p.x;
            ex = __int_as_float(p.y);
        }
        sum += ex;
        int cnt = min(32, e - base);
        int j = 0;
        for (; j + 7 < cnt; j += 8) {
            float e0 = __shfl_sync(FULL, ex, j     + half);
            int   k0 = __shfl_sync(FULL, kn, j     + half);
            float e1 = __shfl_sync(FULL, ex, j + 2 + half);
            int   k1 = __shfl_sync(FULL, kn, j + 2 + half);
            float e2 = __shfl_sync(FULL, ex, j + 4 + half);
            int   k2 = __shfl_sync(FULL, kn, j + 4 + half);
            float e3 = __shfl_sync(FULL, ex, j + 6 + half);
            int   k3 = __shfl_sync(FULL, kn, j + 6 + half);
            float4 v0 = kp4[(size_t)k0 * 16 + hl];
            float4 v1 = kp4[(size_t)k1 * 16 + hl];
            float4 v2 = kp4[(size_t)k2 * 16 + hl];
            float4 v3 = kp4[(size_t)k3 * 16 + hl];
            acc.x += e0 * v0.x; acc.y += e0 * v0.y; acc.z += e0 * v0.z; acc.w += e0 * v0.w;
            acc.x += e1 * v1.x; acc.y += e1 * v1.y; acc.z += e1 * v1.z; acc.w += e1 * v1.w;
            acc.x += e2 * v2.x; acc.y += e2 * v2.y; acc.z += e2 * v2.z; acc.w += e2 * v2.w;
            acc.x += e3 * v3.x; acc.y += e3 * v3.y; acc.z += e3 * v3.z; acc.w += e3 * v3.w;
        }
        for (; j < cnt; j += 2) {
            // j+1 may be == cnt: that lane holds ex=0/kn=0 when cnt<32, and
            // j+1 <= 31 always since pair-steps start at even j < cnt <= 32.
            float e0 = __shfl_sync(FULL, ex, j + half);
            int   k0 = __shfl_sync(FULL, kn, j + half);
            float4 v0 = kp4[(size_t)k0 * 16 + hl];
            acc.x += e0 * v0.x; acc.y += e0 * v0.y; acc.z += e0 * v0.z; acc.w += e0 * v0.w;
        }
    }
    #pragma unroll
    for (int o = 16; o; o >>= 1) sum += __shfl_xor_sync(FULL, sum, o);
    // combine the two halves (partner lane = lane ^ 16)
    acc.x += __shfl_xor_sync(FULL, acc.x, 16);
    acc.y += __shfl_xor_sync(FULL, acc.y, 16);
    acc.z += __shfl_xor_sync(FULL, acc.z, 16);
    acc.w += __shfl_xor_sync(FULL, acc.w, 16);
    float inv = 1.0f / (sum + 1e-10f);   // EPS from reference
    if (half == 0) {
        ((float4*)out)[(size_t)w * 16 + hl] =
            make_float4(acc.x * inv, acc.y * inv, acc.z * inv, acc.w * inv);
    }
}

// ---------- launch ----------
extern "C" void kernel_launch(void* const* d_in, const int* in_sizes, int n_in,
                              void* d_out, int out_size) {
    const float* q  = (const float*)d_in[0];      // query_nodes (Nq,64)
    const float* kv = (const float*)d_in[1];      // key_value_nodes (Nk,64)
    const int*   ei = (const int*)d_in[2];        // edge_index (2,E) int32
    const float* W  = (const float*)d_in[3];      // proj_w (64,64)
    const float* pb = (const float*)d_in[4];      // proj_b (64)
    const float* aw = (const float*)d_in[5];      // attend_w (1,128)
    const float* ab = (const float*)d_in[6];      // attend_b (1)
    float* out = (float*)d_out;

    int Nq = in_sizes[0] / 64;
    int Nk = in_sizes[1] / 64;
    int E  = in_sizes[2] / 2;
    int nb = (Nq + 1023) / 1024;

    k_prep<<<(Nq + 255) / 256, 256>>>(W, pb, aw, ab, Nq);
    k_node_scalars<<<(Nq + 7) / 8, 256>>>(q, Nq);
    k_gemm<<<(Nk + 127) / 128, 256>>>(kv, W, pb, Nk);   // also fills g_sk
    k_edge1<<<(E / 4 + 255) / 256, 256>>>(ei, E);
    k_scan_a<<<nb, 1024>>>(Nq);
    k_scan_c<<<(Nq + 255) / 256, 256>>>(Nq, E, nb);
    k_scatter<<<(E / 4 + 255) / 256, 256>>>(ei, E);
    k_agg<<<(Nq + 7) / 8, 256>>>(out, Nq);
}

// round 9
// speedup vs baseline: 1.2382x; 1.2382x over previous
#include <cuda_runtime.h>

#define NQ_MAX 131072
#define E_MAX  2097152
#define FULL 0xffffffffu

// ---------- device scratch (no allocations allowed) ----------
// invariant: g_count is all-zero at kernel_launch entry (zero-initialized, and
// k_scan_a re-zeroes each element right after reading it).
__device__ int   g_count[NQ_MAX];
__device__ int   g_off[NQ_MAX + 1];
__device__ int   g_cursor[NQ_MAX];
__device__ int   g_bsum[1024];
__device__ __align__(16) float g_sq[NQ_MAX];   // q.u + C (C folded in)
__device__ __align__(16) float g_sk[NQ_MAX];   // kv.v
__device__ __align__(16) int   g_ki[E_MAX];    // sorted key index
__device__ __align__(16) float g_kp[(size_t)NQ_MAX * 64];  // kv_proj

// ---------- kernels ----------
// degree histogram over qi, 4 edges per thread (g_count starts zero: invariant)
__global__ void k_edge1(const int* __restrict__ eidx, int E) {
    int j4 = (blockIdx.x * blockDim.x + threadIdx.x) * 4;
    if (j4 + 3 < E) {
        int4 v = *(const int4*)(eidx + j4);
        atomicAdd(&g_count[v.x], 1);
        atomicAdd(&g_count[v.y], 1);
        atomicAdd(&g_count[v.z], 1);
        atomicAdd(&g_count[v.w], 1);
    } else {
        for (int j = j4; j < E; j++) atomicAdd(&g_count[eidx[j]], 1);
    }
}

// block-level exclusive scan -> g_off (block-local), g_bsum; restores g_count=0
__global__ void k_scan_a(int Nq) {
    __shared__ int wsum[32];
    int tid  = threadIdx.x;
    int lane = tid & 31;
    int wid  = tid >> 5;
    int i = blockIdx.x * 1024 + tid;
    int x = 0;
    if (i < Nq) { x = g_count[i]; g_count[i] = 0; }   // read + restore invariant
    int v = x;
    #pragma unroll
    for (int o = 1; o < 32; o <<= 1) {
        int t = __shfl_up_sync(FULL, v, o);
        if (lane >= o) v += t;
    }
    if (lane == 31) wsum[wid] = v;
    __syncthreads();
    if (wid == 0) {
        int w = wsum[lane];
        #pragma unroll
        for (int o = 1; o < 32; o <<= 1) {
            int t = __shfl_up_sync(FULL, w, o);
            if (lane >= o) w += t;
        }
        wsum[lane] = w;
    }
    __syncthreads();
    int incl = v + (wid ? wsum[wid - 1] : 0);
    if (i < Nq) g_off[i] = incl - x;
    if (tid == 1023) g_bsum[blockIdx.x] = incl;
}

// fused: scan g_bsum (per-block recompute, nb <= 1024) + add to offsets + init cursor
__global__ void k_scan_c(int Nq, int E, int nb) {
    __shared__ int spref[1024];
    int tid = threadIdx.x;       // 256 threads
    for (int t = tid; t < nb; t += 256) spref[t] = g_bsum[t];
    __syncthreads();
    for (int off = 1; off < nb; off <<= 1) {
        int t0 = (tid < nb && tid >= off) ? spref[tid - off] : 0;
        int t1 = (256 + tid < nb && 256 + tid >= off) ? spref[256 + tid - off] : 0;
        int t2 = (512 + tid < nb && 512 + tid >= off) ? spref[512 + tid - off] : 0;
        int t3 = (768 + tid < nb && 768 + tid >= off) ? spref[768 + tid - off] : 0;
        __syncthreads();
        if (tid < nb) spref[tid] += t0;
        if (256 + tid < nb) spref[256 + tid] += t1;
        if (512 + tid < nb) spref[512 + tid] += t2;
        if (768 + tid < nb) spref[768 + tid] += t3;
        __syncthreads();
    }
    int i = blockIdx.x * blockDim.x + tid;
    if (i < Nq) {
        int b = i >> 10;
        int off = g_off[i] + (b ? spref[b - 1] : 0);
        g_off[i] = off;
        g_cursor[i] = off;
    }
    if (i == 0) g_off[Nq] = E;
}

// counting-sort scatter: place ki into qi-contiguous segment (4B payload only).
// 4 edges per thread for MLP on the atomic->store chains. (profiled slot: idx 3)
__global__ void k_scatter(const int* __restrict__ eidx, int E) {
    int j4 = (blockIdx.x * blockDim.x + threadIdx.x) * 4;
    if (((E & 3) == 0) && (j4 + 3 < E)) {
        int4 qq = *(const int4*)(eidx + j4);
        int4 kk = *(const int4*)(eidx + E + j4);
        int p0 = atomicAdd(&g_cursor[qq.x], 1);
        int p1 = atomicAdd(&g_cursor[qq.y], 1);
        int p2 = atomicAdd(&g_cursor[qq.z], 1);
        int p3 = atomicAdd(&g_cursor[qq.w], 1);
        g_ki[p0] = kk.x;
        g_ki[p1] = kk.y;
        g_ki[p2] = kk.z;
        g_ki[p3] = kk.w;
    } else {
        for (int j = j4; j < E && j < j4 + 4; j++) {
            int pos = atomicAdd(&g_cursor[eidx[j]], 1);
            g_ki[pos] = eidx[E + j];
        }
    }
}

// g_sq = q.u + C. u and C computed per block (W is L2-hot, 98 blocks only).
__global__ void k_node_scalars(const float* __restrict__ q, const float* __restrict__ W,
                               const float* __restrict__ pb, const float* __restrict__ aw,
                               const float* __restrict__ ab, int Nq) {
    __shared__ __align__(16) float su[64];
    __shared__ float sC;
    int tid = threadIdx.x;
    if (tid < 64) {
        float uj = 0.f;
        for (int r = 0; r < 64; r++) uj += W[r * 64 + tid] * aw[r];
        su[tid] = uj;
    }
    if (tid == 64) {
        float c = ab[0];
        for (int r = 0; r < 64; r++) c += pb[r] * (aw[r] + aw[64 + r]);
        sC = c;
    }
    __syncthreads();
    int lane = tid & 31;
    int warp = blockIdx.x * (blockDim.x >> 5) + (tid >> 5);
    int nwarps = gridDim.x * (blockDim.x >> 5);
    float2 b = *(const float2*)(su + lane * 2);
    for (int w = warp; w < Nq; w += nwarps) {
        float2 a = *(const float2*)(q + (size_t)w * 64 + lane * 2);
        float acc = a.x * b.x + a.y * b.y;
        #pragma unroll
        for (int o = 16; o; o >>= 1) acc += __shfl_xor_sync(FULL, acc, o);
        if (lane == 0) g_sq[w] = acc + sC;
    }
}

// kv_proj = kv @ W^T + b (64-row tile, 4 rows x 4 cols per thread -> 2 B/FMA LDS)
// fused: g_sk = kv . v (v computed per block from Wts)
__global__ void k_gemm(const float* __restrict__ x, const float* __restrict__ W,
                       const float* __restrict__ b, const float* __restrict__ aw,
                       int Nk) {
    __shared__ __align__(16) float Wts[64 * 64];  // Wts[j*64+i] = W[i*64+j]
    __shared__ __align__(16) float xs[64 * 68];   // padded stride 68 (bank-safe)
    __shared__ __align__(16) float vs[64];
    int tid = threadIdx.x;
    for (int t = tid * 4; t < 4096; t += 1024) {
        float4 w = *(const float4*)(W + t);
        int i = t >> 6, j = t & 63;
        Wts[(j + 0) * 64 + i] = w.x;
        Wts[(j + 1) * 64 + i] = w.y;
        Wts[(j + 2) * 64 + i] = w.z;
        Wts[(j + 3) * 64 + i] = w.w;
    }
    __syncthreads();
    if (tid < 64) {   // v_j = sum_i W[i][j]*aw2[i] = row j of Wts . aw2
        float vj = 0.f;
        for (int i = 0; i < 64; i++) vj += Wts[tid * 64 + i] * aw[64 + i];
        vs[tid] = vj;
    }
    __syncthreads();
    int r  = tid >> 4;   // 0..15
    int cg = tid & 15;   // 0..15 -> cols cg*4..cg*4+3
    float4 bias = *(const float4*)(b + cg * 4);
    float4 vv   = *(const float4*)(vs + cg * 4);
    int base = blockIdx.x * 64;
    // load 4 rows (r, r+16, r+32, r+48) + fused sk partial
    #pragma unroll
    for (int l = 0; l < 4; l++) {
        int row = base + r + l * 16;
        float4 xv = (row < Nk) ? *(const float4*)(x + (size_t)row * 64 + cg * 4)
                               : make_float4(0.f, 0.f, 0.f, 0.f);
        *(float4*)(xs + (r + l * 16) * 68 + cg * 4) = xv;
        float p = xv.x * vv.x + xv.y * vv.y + xv.z * vv.z + xv.w * vv.w;
        #pragma unroll
        for (int o = 8; o; o >>= 1) p += __shfl_xor_sync(FULL, p, o);
        if (cg == 0 && row < Nk) g_sk[row] = p;
    }
    __syncthreads();
    float4 a0 = bias, a1 = bias, a2 = bias, a3 = bias;
    #pragma unroll
    for (int j = 0; j < 64; j++) {
        float4 wv = *(const float4*)(Wts + j * 64 + cg * 4);
        float x0 = xs[(r     ) * 68 + j];
        float x1 = xs[(r + 16) * 68 + j];
        float x2 = xs[(r + 32) * 68 + j];
        float x3 = xs[(r + 48) * 68 + j];
        a0.x += x0 * wv.x; a0.y += x0 * wv.y; a0.z += x0 * wv.z; a0.w += x0 * wv.w;
        a1.x += x1 * wv.x; a1.y += x1 * wv.y; a1.z += x1 * wv.z; a1.w += x1 * wv.w;
        a2.x += x2 * wv.x; a2.y += x2 * wv.y; a2.z += x2 * wv.z; a2.w += x2 * wv.w;
        a3.x += x3 * wv.x; a3.y += x3 * wv.y; a3.z += x3 * wv.z; a3.w += x3 * wv.w;
    }
    int row0 = base + r;
    if (row0      < Nk) *(float4*)(g_kp + (size_t)(row0     ) * 64 + cg * 4) = a0;
    if (row0 + 16 < Nk) *(float4*)(g_kp + (size_t)(row0 + 16) * 64 + cg * 4) = a1;
    if (row0 + 32 < Nk) *(float4*)(g_kp + (size_t)(row0 + 32) * 64 + cg * 4) = a2;
    if (row0 + 48 < Nk) *(float4*)(g_kp + (size_t)(row0 + 48) * 64 + cg * 4) = a3;
}

// warp per query node: lane i computes ex = exp(leaky(sq + sk[ki])) for its edge,
// then shfl-broadcast + float2 gathers (R7-proven structure, 4-way unrolled).
__global__ void k_agg(float* __restrict__ out, int Nq) {
    int w = (blockIdx.x * blockDim.x + threadIdx.x) >> 5;
    int lane = threadIdx.x & 31;
    if (w >= Nq) return;
    int s = g_off[w], e = g_off[w + 1];
    float sqc = g_sq[w];   // includes +C
    const float2* kp_l = (const float2*)g_kp + lane;   // row k at kp_l[k*32]
    float sum = 0.f, ax = 0.f, ay = 0.f;
    for (int base = s; base < e; base += 32) {
        int i = base + lane;
        float ex = 0.f; int kn = 0;
        if (i < e) {
            kn = g_ki[i];
            float ev = sqc + g_sk[kn];
            ev = ev > 0.f ? ev : 0.2f * ev;      // leaky relu, alpha 0.2
            ex = __expf(ev);
        }
        sum += ex;
        int cnt = min(32, e - base);
        int j = 0;
        for (; j + 3 < cnt; j += 4) {
            float e0 = __shfl_sync(FULL, ex, j);
            float e1 = __shfl_sync(FULL, ex, j + 1);
            float e2 = __shfl_sync(FULL, ex, j + 2);
            float e3 = __shfl_sync(FULL, ex, j + 3);
            int   k0 = __shfl_sync(FULL, kn, j);
            int   k1 = __shfl_sync(FULL, kn, j + 1);
            int   k2 = __shfl_sync(FULL, kn, j + 2);
            int   k3 = __shfl_sync(FULL, kn, j + 3);
            float2 v0 = kp_l[(size_t)k0 * 32];
            float2 v1 = kp_l[(size_t)k1 * 32];
            float2 v2 = kp_l[(size_t)k2 * 32];
            float2 v3 = kp_l[(size_t)k3 * 32];
            ax += e0 * v0.x; ay += e0 * v0.y;
            ax += e1 * v1.x; ay += e1 * v1.y;
            ax += e2 * v2.x; ay += e2 * v2.y;
            ax += e3 * v3.x; ay += e3 * v3.y;
        }
        for (; j < cnt; j++) {
            float e0 = __shfl_sync(FULL, ex, j);
            int   k0 = __shfl_sync(FULL, kn, j);
            float2 v0 = kp_l[(size_t)k0 * 32];
            ax += e0 * v0.x; ay += e0 * v0.y;
        }
    }
    #pragma unroll
    for (int o = 16; o; o >>= 1) sum += __shfl_xor_sync(FULL, sum, o);
    float inv = 1.0f / (sum + 1e-10f);   // EPS from reference
    *(float2*)(out + (size_t)w * 64 + lane * 2) = make_float2(ax * inv, ay * inv);
}

// ---------- launch ----------
extern "C" void kernel_launch(void* const* d_in, const int* in_sizes, int n_in,
                              void* d_out, int out_size) {
    const float* q  = (const float*)d_in[0];      // query_nodes (Nq,64)
    const float* kv = (const float*)d_in[1];      // key_value_nodes (Nk,64)
    const int*   ei = (const int*)d_in[2];        // edge_index (2,E) int32
    const float* W  = (const float*)d_in[3];      // proj_w (64,64)
    const float* pb = (const float*)d_in[4];      // proj_b (64)
    const float* aw = (const float*)d_in[5];      // attend_w (1,128)
    const float* ab = (const float*)d_in[6];      // attend_b (1)
    float* out = (float*)d_out;

    int Nq = in_sizes[0] / 64;
    int Nk = in_sizes[1] / 64;
    int E  = in_sizes[2] / 2;
    int nb = (Nq + 1023) / 1024;

    k_edge1<<<(E / 4 + 255) / 256, 256>>>(ei, E);                 // idx 0
    k_scan_a<<<nb, 1024>>>(Nq);                                   // idx 1
    k_scan_c<<<(Nq + 255) / 256, 256>>>(Nq, E, nb);               // idx 2
    k_scatter<<<(E / 4 + 255) / 256, 256>>>(ei, E);               // idx 3 (profiled)
    k_node_scalars<<<98, 1024>>>(q, W, pb, aw, ab, Nq);           // idx 4
    k_gemm<<<(Nk + 63) / 64, 256>>>(kv, W, pb, aw, Nk);           // idx 5
    k_agg<<<(Nq + 7) / 8, 256>>>(out, Nq);                        // idx 6
}